// round 10
// baseline (speedup 1.0000x reference)
#include <cuda_runtime.h>
#include <cuda_bf16.h>
#include <cstdint>
#include <cstddef>

// Problem constants (fixed by the reference).
#define NN   8192   // N_NODES
#define INF  256    // IN_FEATURES
#define OUTF 32     // OUT_FEATURES

// ---------------------------------------------------------------------------
// Scratch: HW = h @ W split into bf16 hi/lo, stored transposed [plane][n][k],
// with a k-permutation within each 16-block so the A operand comes straight
// from gmem as one LDG.128 per lane per (kstep,row):
//   pos(k) = (k&2 ? 8 : 0) + ((k>>2)<<1) + (k&1)
// ---------------------------------------------------------------------------
__device__ __nv_bfloat16 g_B[2 * OUTF * NN];

// ---------------------------------------------------------------------------
// Kernel 1: HW = h @ W (fp32) -> hi/lo bf16 planes in g_B (permuted k).
// Also zero-inits out. Signals PDL dependents immediately at entry.
// Grid 256 x 256 thr; block = 32 rows; thread = 1 row x 4 output features.
// h tile staged coalesced in smem (pitch 257 -> conflict-free); W read via
// L1-broadcast LDG.128 (32 KB, L1-resident).
// ---------------------------------------------------------------------------
__global__ void __launch_bounds__(256) hw_kernel(const float* __restrict__ h,
                                                 const float* __restrict__ W,
                                                 float* __restrict__ out) {
    asm volatile("griddepcontrol.launch_dependents;" ::: "memory");
    __shared__ float sh[32 * 257];
    const int t = threadIdx.x;

    // Zero-init out: 65536 threads x 1 float4 = 262144 floats exactly.
    reinterpret_cast<float4*>(out)[blockIdx.x * 256 + t] = make_float4(0.f, 0.f, 0.f, 0.f);

    // Stage h tile [32 x 256] coalesced.
    const int rbase = blockIdx.x * 32;
    for (int i = t; i < 32 * 64; i += 256) {
        const int row = i >> 6, seg = i & 63;
        const float4 v = reinterpret_cast<const float4*>(h + (size_t)(rbase + row) * INF)[seg];
        float* d = &sh[row * 257 + seg * 4];
        d[0] = v.x; d[1] = v.y; d[2] = v.z; d[3] = v.w;
    }
    __syncthreads();

    const int row = t & 31;                 // lane -> row (conflict-free LDS)
    const int n0  = (t >> 5) * 4;           // warp -> 4 output features
    const float* hr = &sh[row * 257];
    float a0 = 0.f, a1 = 0.f, a2 = 0.f, a3 = 0.f;
#pragma unroll 8
    for (int k = 0; k < INF; ++k) {
        const float hv = hr[k];
        const float4 w4 = *reinterpret_cast<const float4*>(W + k * OUTF + n0);  // warp-broadcast
        a0 += hv * w4.x; a1 += hv * w4.y; a2 += hv * w4.z; a3 += hv * w4.w;
    }

    const int grow = rbase + row;
    const int ph   = grow & 15;
    const int p    = ((ph & 2) ? 8 : 0) | ((ph >> 2) << 1) | (ph & 1);
    const int kpos = (grow & ~15) | p;
    const float acc[4] = {a0, a1, a2, a3};
#pragma unroll
    for (int j = 0; j < 4; ++j) {
        const __nv_bfloat16 hi = __float2bfloat16_rn(acc[j]);
        const float rem        = acc[j] - __bfloat162float(hi);
        g_B[(size_t)(n0 + j) * NN + kpos]        = hi;                        // hi plane
        g_B[(size_t)(OUTF + n0 + j) * NN + kpos] = __float2bfloat16_rn(rem);  // lo plane
    }
}

// ---------------------------------------------------------------------------
// Kernel 2: out += adj @ HW via bf16 mma.sync (hi+lo planes).
//
// Grid = 512: 64 m-tiles (BM=128) x 8 K-splits (1024 K each).
// CTA = 128 thr = 4 warps; warp w = rows [w*32, w*32+32) x ALL n=32:
// B fragments are loaded once per k-step and reused for BOTH m16-tiles,
// halving smem B wavefronts per adj byte (the R9 L1TEX bottleneck).
//
// A: direct gmem fragments, rolling k-step prefetch (distance 2, 32 regs).
// B: 3-stage cp.async ring, ONE __syncthreads per 64-wide chunk.
// PDL: first A prefetches issue before griddepcontrol.wait (overlap hw).
// ---------------------------------------------------------------------------
#define BK      64
#define PITCH   144                    // bytes per B smem row (64 halfs + pad)
#define STAGEB  (64 * PITCH)           // 9216 B per stage (2 planes x 32 n)
#define KSPLIT  8
#define KPER    (NN / KSPLIT)          // 1024
#define CH      (KPER / BK)            // 16 chunks
#define GSTEPS  (KPER / 16)            // 64 k-steps

#define MMA_BF16(ACC, A0, A1, A2, A3, B0, B1)                                   \
    asm volatile("mma.sync.aligned.m16n8k16.row.col.f32.bf16.bf16.f32 "         \
                 "{%0,%1,%2,%3}, {%4,%5,%6,%7}, {%8,%9}, {%0,%1,%2,%3};\n"      \
                 : "+f"((ACC)[0]), "+f"((ACC)[1]), "+f"((ACC)[2]), "+f"((ACC)[3])\
                 : "r"(A0), "r"(A1), "r"(A2), "r"(A3), "r"(B0), "r"(B1))

#define LDMX4(R0, R1, R2, R3, ADDR)                                             \
    asm volatile("ldmatrix.sync.aligned.m8n8.x4.shared.b16 {%0,%1,%2,%3}, [%4];\n"\
                 : "=r"(R0), "=r"(R1), "=r"(R2), "=r"(R3) : "r"(ADDR))

__global__ void __launch_bounds__(128) spmm_kernel(const float* __restrict__ adj,
                                                   float* __restrict__ out) {
    __shared__ __align__(16) char smem[3 * STAGEB];   // 27648 B
    const uint32_t sb0 = static_cast<uint32_t>(__cvta_generic_to_shared(smem));

    const int t    = threadIdx.x;
    const int lane = t & 31;
    const int wm   = t >> 5;                    // 4 warps, m32 each
    const int mt   = blockIdx.x >> 3;           // m-tile 0..63
    const int ksid = blockIdx.x & 7;            // K-split id
    const int ctaM = mt * 128;
    const int kbase = ksid * KPER;

    // A addressing: lane -> rows {r, r+8, r+16, r+24}, cols 4*(lane&3) per k16.
    const int r  = lane >> 2;
    const int c4 = (lane & 3) << 2;
    const float* aptr = adj + (size_t)(ctaM + wm * 32 + r) * NN + kbase + c4;

    float4 pf[2][4];                            // rolling A prefetch, distance 2
    auto ldk = [&](int g, float4* dst) {
        const float* p = aptr + g * 16;
        dst[0] = *reinterpret_cast<const float4*>(p);
        dst[1] = *reinterpret_cast<const float4*>(p + (size_t)8  * NN);
        dst[2] = *reinterpret_cast<const float4*>(p + (size_t)16 * NN);
        dst[3] = *reinterpret_cast<const float4*>(p + (size_t)24 * NN);
    };

    // B cp.async: 64 rows x 128B per chunk; 512 x 16B ops, 4 per thread.
    auto cp_b = [&](int chunk, int stage) {
        if (chunk < CH) {
            const uint32_t bo = sb0 + (uint32_t)stage * STAGEB;
            const __nv_bfloat16* s0 = g_B + kbase + chunk * BK;
#pragma unroll
            for (int i = 0; i < 4; ++i) {
                const int idx = t + i * 128;
                const int row = idx >> 3;       // 0..63 = plane*32 + n
                const int seg = idx & 7;
                const void* src = s0 + (size_t)row * NN + seg * 8;
                const uint32_t dst = bo + row * PITCH + seg * 16;
                asm volatile("cp.async.cg.shared.global [%0], [%1], 16;\n"
                             :: "r"(dst), "l"(src));
            }
        }
        asm volatile("cp.async.commit_group;\n" ::);
    };

    // B ldmatrix lane offset (warp-independent: all warps share B).
    const uint32_t brow = (uint32_t)(((lane >> 4) << 3) + (lane & 7));
    const uint32_t bko  = (uint32_t)(((lane >> 3) & 1) << 4);
    const uint32_t boff = brow * PITCH + bko;

    float acc[2][4][4] = {};                    // [m-tile][n8-tile][frag]

    // ---- PDL: A prefetches first (adj independent of hw), then wait for g_B.
    ldk(0, pf[0]);
    ldk(1, pf[1]);
    asm volatile("griddepcontrol.wait;" ::: "memory");
    cp_b(0, 0); cp_b(1, 1);

    int s_cur = 0;                              // stage holding 'chunk'
    for (int chunk = 0; chunk < CH; ++chunk) {
        asm volatile("cp.async.wait_group 1;\n" ::);   // B(chunk) arrived
        __syncthreads();                               // stage(chunk-1) reusable
        int s_nxt = s_cur + 2; if (s_nxt >= 3) s_nxt -= 3;
        cp_b(chunk + 2, s_nxt);

        const uint32_t sb = sb0 + (uint32_t)s_cur * STAGEB;
#pragma unroll
        for (int ks = 0; ks < 4; ++ks) {
            const int g = chunk * 4 + ks;
            float4* f = pf[g & 1];
            // Convert A fragments for both m-tiles (0/1 exact in bf16).
            __nv_bfloat162 b;
            uint32_t q[8];
            b = __floats2bfloat162_rn(f[0].x, f[0].y); q[0] = *reinterpret_cast<uint32_t*>(&b);
            b = __floats2bfloat162_rn(f[1].x, f[1].y); q[1] = *reinterpret_cast<uint32_t*>(&b);
            b = __floats2bfloat162_rn(f[0].z, f[0].w); q[2] = *reinterpret_cast<uint32_t*>(&b);
            b = __floats2bfloat162_rn(f[1].z, f[1].w); q[3] = *reinterpret_cast<uint32_t*>(&b);
            b = __floats2bfloat162_rn(f[2].x, f[2].y); q[4] = *reinterpret_cast<uint32_t*>(&b);
            b = __floats2bfloat162_rn(f[3].x, f[3].y); q[5] = *reinterpret_cast<uint32_t*>(&b);
            b = __floats2bfloat162_rn(f[2].z, f[2].w); q[6] = *reinterpret_cast<uint32_t*>(&b);
            b = __floats2bfloat162_rn(f[3].z, f[3].w); q[7] = *reinterpret_cast<uint32_t*>(&b);
            if (g + 2 < GSTEPS) ldk(g + 2, pf[g & 1]);     // keep 2 k-steps in flight

            uint32_t h0,h1,h2,h3,h4,h5,h6,h7, l0,l1,l2,l3,l4,l5,l6,l7;
            const uint32_t ko = boff + ks * 32;
            LDMX4(h0,h1,h2,h3, sb + ko);                    // hi, n0-15
            LDMX4(h4,h5,h6,h7, sb + 16 * PITCH + ko);       // hi, n16-31
            LDMX4(l0,l1,l2,l3, sb + 32 * PITCH + ko);       // lo, n0-15
            LDMX4(l4,l5,l6,l7, sb + 48 * PITCH + ko);       // lo, n16-31

            // m-tile 0 (rows r, r+8) — B fragments reused below for m-tile 1.
            MMA_BF16(acc[0][0], q[0],q[1],q[2],q[3], h0,h1);
            MMA_BF16(acc[0][0], q[0],q[1],q[2],q[3], l0,l1);
            MMA_BF16(acc[0][1], q[0],q[1],q[2],q[3], h2,h3);
            MMA_BF16(acc[0][1], q[0],q[1],q[2],q[3], l2,l3);
            MMA_BF16(acc[0][2], q[0],q[1],q[2],q[3], h4,h5);
            MMA_BF16(acc[0][2], q[0],q[1],q[2],q[3], l4,l5);
            MMA_BF16(acc[0][3], q[0],q[1],q[2],q[3], h6,h7);
            MMA_BF16(acc[0][3], q[0],q[1],q[2],q[3], l6,l7);
            // m-tile 1 (rows r+16, r+24).
            MMA_BF16(acc[1][0], q[4],q[5],q[6],q[7], h0,h1);
            MMA_BF16(acc[1][0], q[4],q[5],q[6],q[7], l0,l1);
            MMA_BF16(acc[1][1], q[4],q[5],q[6],q[7], h2,h3);
            MMA_BF16(acc[1][1], q[4],q[5],q[6],q[7], l2,l3);
            MMA_BF16(acc[1][2], q[4],q[5],q[6],q[7], h4,h5);
            MMA_BF16(acc[1][2], q[4],q[5],q[6],q[7], l4,l5);
            MMA_BF16(acc[1][3], q[4],q[5],q[6],q[7], h6,h7);
            MMA_BF16(acc[1][3], q[4],q[5],q[6],q[7], l6,l7);
        }
        s_cur = s_cur + 1 == 3 ? 0 : s_cur + 1;
    }

    // ---- Epilogue: accumulate K-split partials with fp32 atomics.
    const int r0 = ctaM + wm * 32 + (lane >> 2);
    const int c0 = (lane & 3) * 2;
#pragma unroll
    for (int m = 0; m < 2; ++m)
#pragma unroll
        for (int nt = 0; nt < 4; ++nt) {
            float* o = out + (size_t)(r0 + m * 16) * OUTF + nt * 8 + c0;
            atomicAdd(o,                acc[m][nt][0]);
            atomicAdd(o + 1,            acc[m][nt][1]);
            atomicAdd(o + 8 * OUTF,     acc[m][nt][2]);
            atomicAdd(o + 8 * OUTF + 1, acc[m][nt][3]);
        }
}

// ---------------------------------------------------------------------------
// Launch: h [8192*256] f32, adj [8192*8192] f32, W [256*32] f32; out f32.
// spmm launched with PDL so it overlaps hw_kernel (safe fallback if refused).
// ---------------------------------------------------------------------------
extern "C" void kernel_launch(void* const* d_in, const int* in_sizes, int n_in,
                              void* d_out, int out_size) {
    (void)in_sizes; (void)n_in; (void)out_size;
    const float* h   = reinterpret_cast<const float*>(d_in[0]);
    const float* adj = reinterpret_cast<const float*>(d_in[1]);
    const float* W   = reinterpret_cast<const float*>(d_in[2]);
    float* out       = reinterpret_cast<float*>(d_out);

    hw_kernel<<<NN / 32, 256>>>(h, W, out);    // 256 blocks: HW pack + out=0

    cudaLaunchConfig_t cfg = {};
    cfg.gridDim  = dim3((NN / 128) * KSPLIT);  // 512 CTAs
    cfg.blockDim = dim3(128);
    cfg.stream   = 0;
    cudaLaunchAttribute at[1];
    at[0].id = cudaLaunchAttributeProgrammaticStreamSerialization;
    at[0].val.programmaticStreamSerializationAllowed = 1;
    cfg.attrs = at;
    cfg.numAttrs = 1;
    if (cudaLaunchKernelEx(&cfg, spmm_kernel, adj, out) != cudaSuccess) {
        spmm_kernel<<<(NN / 128) * KSPLIT, 128>>>(adj, out);   // plain fallback
    }
}

// round 11
// speedup vs baseline: 1.5890x; 1.5890x over previous
#include <cuda_runtime.h>
#include <cuda_bf16.h>
#include <cstdint>
#include <cstddef>

// Problem constants (fixed by the reference).
#define NN   8192   // N_NODES
#define INF  256    // IN_FEATURES
#define OUTF 32     // OUT_FEATURES

// ---------------------------------------------------------------------------
// Scratch: HW = h @ W split into bf16 hi/lo, stored transposed [plane][n][k],
// with a k-permutation within each 16-block so the A operand comes straight
// from gmem as one LDG.128 per lane per (kstep,row):
//   pos(k) = (k&2 ? 8 : 0) + ((k>>2)<<1) + (k&1)
// ---------------------------------------------------------------------------
__device__ __nv_bfloat16 g_B[2 * OUTF * NN];

// ---------------------------------------------------------------------------
// Kernel 1: HW = h @ W (fp32) -> hi/lo bf16 planes in g_B (permuted k).
// Also zero-inits out. Grid 256 x 256 thr; block = 32 rows; thread = 1 row x
// 4 output features. h staged coalesced in smem (pitch 257, conflict-free);
// W read via L1-broadcast LDG.128. ~5-6 us.
// ---------------------------------------------------------------------------
__global__ void __launch_bounds__(256) hw_kernel(const float* __restrict__ h,
                                                 const float* __restrict__ W,
                                                 float* __restrict__ out) {
    __shared__ float sh[32 * 257];
    const int t = threadIdx.x;

    // Zero-init out: 65536 threads x 1 float4 = 262144 floats exactly.
    reinterpret_cast<float4*>(out)[blockIdx.x * 256 + t] = make_float4(0.f, 0.f, 0.f, 0.f);

    // Stage h tile [32 x 256] coalesced.
    const int rbase = blockIdx.x * 32;
    for (int i = t; i < 32 * 64; i += 256) {
        const int row = i >> 6, seg = i & 63;
        const float4 v = reinterpret_cast<const float4*>(h + (size_t)(rbase + row) * INF)[seg];
        float* d = &sh[row * 257 + seg * 4];
        d[0] = v.x; d[1] = v.y; d[2] = v.z; d[3] = v.w;
    }
    __syncthreads();

    const int row = t & 31;                 // lane -> row (conflict-free LDS)
    const int n0  = (t >> 5) * 4;           // warp -> 4 output features
    const float* hr = &sh[row * 257];
    float a0 = 0.f, a1 = 0.f, a2 = 0.f, a3 = 0.f;
#pragma unroll 8
    for (int k = 0; k < INF; ++k) {
        const float hv = hr[k];
        const float4 w4 = *reinterpret_cast<const float4*>(W + k * OUTF + n0);  // warp-broadcast
        a0 += hv * w4.x; a1 += hv * w4.y; a2 += hv * w4.z; a3 += hv * w4.w;
    }

    const int grow = rbase + row;
    const int ph   = grow & 15;
    const int p    = ((ph & 2) ? 8 : 0) | ((ph >> 2) << 1) | (ph & 1);
    const int kpos = (grow & ~15) | p;
    const float acc[4] = {a0, a1, a2, a3};
#pragma unroll
    for (int j = 0; j < 4; ++j) {
        const __nv_bfloat16 hi = __float2bfloat16_rn(acc[j]);
        const float rem        = acc[j] - __bfloat162float(hi);
        g_B[(size_t)(n0 + j) * NN + kpos]        = hi;                        // hi plane
        g_B[(size_t)(OUTF + n0 + j) * NN + kpos] = __float2bfloat16_rn(rem);  // lo plane
    }
}

// ---------------------------------------------------------------------------
// Kernel 2: out += adj_chunk @ HW via bf16 mma.sync (hi+lo planes).
// == The proven 52.6us configuration (round-5 submission), with KSPLIT 4->8
//    (grid 512->1024: lift the grid-limited 3.46 CTAs/SM to ~4.6) and a
//    red.v2.f32 epilogue. NO register cap (the round-6 regression).
//
// Grid = 1024 CTAs: 128 m-tiles (BM=64) x 8 K-splits (1024 K each).
// CTA = 128 threads = 4 warps; warp w owns rows [w*16, w*16+16) x all n=32.
// A: direct gmem fragments (2 coalesced LDG.128 per lane per k16), whole-chunk
//    register prefetch, distance 1.
// B: 4-stage cp.async ring (36.9KB), prefetch depth 3, ONE syncthreads/chunk.
// ---------------------------------------------------------------------------
#define BK      64
#define PITCH   144                    // bytes per B smem row (64 halfs + pad)
#define STAGEB  (64 * PITCH)           // 9216 B per stage (2 planes x 32 n)
#define KSPLIT  8
#define KPER    (NN / KSPLIT)          // 1024
#define CH      (KPER / BK)            // 16 chunks per CTA

#define MMA_BF16(ACC, A0, A1, A2, A3, B0, B1)                                   \
    asm volatile("mma.sync.aligned.m16n8k16.row.col.f32.bf16.bf16.f32 "         \
                 "{%0,%1,%2,%3}, {%4,%5,%6,%7}, {%8,%9}, {%0,%1,%2,%3};\n"      \
                 : "+f"((ACC)[0]), "+f"((ACC)[1]), "+f"((ACC)[2]), "+f"((ACC)[3])\
                 : "r"(A0), "r"(A1), "r"(A2), "r"(A3), "r"(B0), "r"(B1))

#define LDMX4(R0, R1, R2, R3, ADDR)                                             \
    asm volatile("ldmatrix.sync.aligned.m8n8.x4.shared.b16 {%0,%1,%2,%3}, [%4];\n"\
                 : "=r"(R0), "=r"(R1), "=r"(R2), "=r"(R3) : "r"(ADDR))

#define REDV2(PTR, X, Y)                                                        \
    asm volatile("red.global.add.v2.f32 [%0], {%1, %2};\n"                      \
                 :: "l"(PTR), "f"(X), "f"(Y) : "memory")

__global__ void __launch_bounds__(128) spmm_kernel(const float* __restrict__ adj,
                                                   float* __restrict__ out) {
    __shared__ __align__(16) char smem[4 * STAGEB];   // 36864 B
    const uint32_t sb0 = static_cast<uint32_t>(__cvta_generic_to_shared(smem));

    const int t    = threadIdx.x;
    const int lane = t & 31;
    const int wm   = t >> 5;                    // 4 m-warps
    const int mt   = blockIdx.x >> 3;           // m-tile 0..127
    const int ksid = blockIdx.x & 7;            // K-split id
    const int ctaM = mt * 64;
    const int kbase = ksid * KPER;

    // ---- A direct-fragment addressing: lane covers row r=lane/4 (and r+8),
    //      float4 at phys cols 4*(lane%4) within each k16 window.
    const int r  = lane >> 2;
    const int c4 = (lane & 3) << 2;
    const float* aptr = adj + (size_t)(ctaM + wm * 16 + r) * NN + kbase + c4;

    float4 pf[8];                               // prefetch: [kstep]{rows r, r+8}
    auto ld_a = [&](int chunk) {
        const float* p = aptr + chunk * BK;
#pragma unroll
        for (int ks = 0; ks < 4; ++ks) {
            pf[2 * ks]     = *reinterpret_cast<const float4*>(p + ks * 16);
            pf[2 * ks + 1] = *reinterpret_cast<const float4*>(p + ks * 16 + (size_t)8 * NN);
        }
    };

    // ---- B cp.async: 64 rows x 128B per chunk; 512 x 16B ops, 4/thread.
    auto cp_b = [&](int chunk) {
        if (chunk < CH) {
            const uint32_t bo = sb0 + (uint32_t)(chunk & 3) * STAGEB;
            const __nv_bfloat16* s0 = g_B + kbase + chunk * BK;
#pragma unroll
            for (int i = 0; i < 4; ++i) {
                const int idx = t + i * 128;
                const int row = idx >> 3;       // 0..63 = plane*32 + n
                const int seg = idx & 7;
                const void* src = s0 + (size_t)row * NN + seg * 8;
                const uint32_t dst = bo + row * PITCH + seg * 16;
                asm volatile("cp.async.cg.shared.global [%0], [%1], 16;\n"
                             :: "r"(dst), "l"(src));
            }
        }
        asm volatile("cp.async.commit_group;\n" ::);
    };

    // ---- B ldmatrix lane offset within a 16-row group.
    const uint32_t brow = (uint32_t)(((lane >> 4) << 3) + (lane & 7));
    const uint32_t bko  = (uint32_t)(((lane >> 3) & 1) << 4);
    const uint32_t boff = brow * PITCH + bko;

    float acc[4][4] = {};                       // 4 n8-tiles
    uint32_t cur[16];                           // chunk's packed bf16 A frags

    ld_a(0);
    cp_b(0); cp_b(1); cp_b(2);                  // B prefetch depth 3

    for (int chunk = 0; chunk < CH; ++chunk) {
        // Convert prefetched A (frees pf for next chunk's loads).
#pragma unroll
        for (int ks = 0; ks < 4; ++ks) {
            const float4 f = pf[2 * ks], g = pf[2 * ks + 1];
            __nv_bfloat162 q0 = __floats2bfloat162_rn(f.x, f.y);   // a0
            __nv_bfloat162 q1 = __floats2bfloat162_rn(g.x, g.y);   // a1 (r+8)
            __nv_bfloat162 q2 = __floats2bfloat162_rn(f.z, f.w);   // a2
            __nv_bfloat162 q3 = __floats2bfloat162_rn(g.z, g.w);   // a3
            cur[4 * ks + 0] = *reinterpret_cast<uint32_t*>(&q0);
            cur[4 * ks + 1] = *reinterpret_cast<uint32_t*>(&q1);
            cur[4 * ks + 2] = *reinterpret_cast<uint32_t*>(&q2);
            cur[4 * ks + 3] = *reinterpret_cast<uint32_t*>(&q3);
        }
        if (chunk + 1 < CH) ld_a(chunk + 1);    // next chunk's A in flight

        asm volatile("cp.async.wait_group 2;\n" ::);   // B(chunk) arrived
        __syncthreads();                        // all warps done with chunk-1
        cp_b(chunk + 3);                        // overwrites chunk-1's stage: safe

        const uint32_t sb = sb0 + (uint32_t)(chunk & 3) * STAGEB;
#pragma unroll
        for (int ks = 0; ks < 4; ++ks) {
            uint32_t h0,h1,h2,h3,h4,h5,h6,h7, l0,l1,l2,l3,l4,l5,l6,l7;
            const uint32_t ko = boff + ks * 32;
            LDMX4(h0,h1,h2,h3, sb + ko);                    // hi, n0-15
            LDMX4(h4,h5,h6,h7, sb + 16 * PITCH + ko);       // hi, n16-31
            LDMX4(l0,l1,l2,l3, sb + 32 * PITCH + ko);       // lo, n0-15
            LDMX4(l4,l5,l6,l7, sb + 48 * PITCH + ko);       // lo, n16-31
            const uint32_t a0 = cur[4*ks], a1 = cur[4*ks+1],
                           a2 = cur[4*ks+2], a3 = cur[4*ks+3];
            MMA_BF16(acc[0], a0,a1,a2,a3, h0,h1);
            MMA_BF16(acc[0], a0,a1,a2,a3, l0,l1);
            MMA_BF16(acc[1], a0,a1,a2,a3, h2,h3);
            MMA_BF16(acc[1], a0,a1,a2,a3, l2,l3);
            MMA_BF16(acc[2], a0,a1,a2,a3, h4,h5);
            MMA_BF16(acc[2], a0,a1,a2,a3, l4,l5);
            MMA_BF16(acc[3], a0,a1,a2,a3, h6,h7);
            MMA_BF16(acc[3], a0,a1,a2,a3, l6,l7);
        }
    }

    // ---- Epilogue: K-split partials via vector reductions (8B-aligned).
    const int row0 = ctaM + wm * 16 + (lane >> 2);
    const int col0 = (lane & 3) * 2;
#pragma unroll
    for (int tile = 0; tile < 4; ++tile) {
        float* o0 = out + (size_t)row0 * OUTF + tile * 8 + col0;
        REDV2(o0,            acc[tile][0], acc[tile][1]);
        REDV2(o0 + 8 * OUTF, acc[tile][2], acc[tile][3]);
    }
}

// ---------------------------------------------------------------------------
// Launch: h [8192*256] f32, adj [8192*8192] f32, W [256*32] f32; out f32.
// Plain launches (PDL regressed badly under graph capture in R10).
// ---------------------------------------------------------------------------
extern "C" void kernel_launch(void* const* d_in, const int* in_sizes, int n_in,
                              void* d_out, int out_size) {
    (void)in_sizes; (void)n_in; (void)out_size;
    const float* h   = reinterpret_cast<const float*>(d_in[0]);
    const float* adj = reinterpret_cast<const float*>(d_in[1]);
    const float* W   = reinterpret_cast<const float*>(d_in[2]);
    float* out       = reinterpret_cast<float*>(d_out);

    hw_kernel<<<NN / 32, 256>>>(h, W, out);                 // HW pack + out=0
    spmm_kernel<<<(NN / 64) * KSPLIT, 128>>>(adj, out);     // 1024 CTAs
}